// round 4
// baseline (speedup 1.0000x reference)
#include <cuda_runtime.h>
#include <cuda_bf16.h>
#include <cstdint>

// Batched greedy nearest-neighbor selection.
// distance: (B, N, N) f32; mask: (B, N) bool (int32/float32/uint8 auto-detected);
// start_idx: (B,) int-or-float (auto-decoded); pad_value: scalar int-or-float (fallback N).
// Output (float32!): pred (B, N) followed by pred_len (B,).
//
// Inputs identified BY SIZE: distance = largest; mask = largest remaining;
// start_idx = size B; pad = size 1.

#define BIGF 1.0e6f
#define NTHREADS 256
#define NWARPS (NTHREADS / 32)
#define MSK_CAP 4096

// Decode a 32-bit word that is either an int32 or a float32 holding a small
// non-negative integer value (0..N). Ints 0..N keep bits <= N; floats >=1.0
// have bits >= 0x3F800000 >> N.
__device__ __forceinline__ int decode_scalar(unsigned int w, int N)
{
    return (w <= (unsigned int)N) ? (int)w : (int)__uint_as_float(w);
}

__global__ __launch_bounds__(NTHREADS, 1)
void greedy_nn_kernel(const float* __restrict__ distance,
                      const unsigned char* __restrict__ mraw,
                      const unsigned int* __restrict__ start_raw,
                      const unsigned int* __restrict__ pad_raw,
                      float* __restrict__ pred,
                      float* __restrict__ pred_len,
                      int N)
{
    __shared__ unsigned char s_msk[MSK_CAP];              // visited flags (N <= 4096)
    __shared__ unsigned long long s_partial[2][NWARPS];   // double-buffered warp minima
    __shared__ int s_warpcnt[NWARPS];
    __shared__ int s_init[3];                             // {word_mode, start_point, rem}

    const int b    = blockIdx.x;
    const int tid  = threadIdx.x;
    const int lane = tid & 31;
    const int wid  = tid >> 5;

    const float* D = distance + (size_t)b * (size_t)N * (size_t)N;
    float* pred_b = pred + (size_t)b * N;
    const int pad = (pad_raw != nullptr) ? decode_scalar(*pad_raw, N) : N;

    // ---- detect mask element width (thread 0) ----
    if (tid == 0) {
        const unsigned int* mw = (const unsigned int*)mraw;
        bool all01 = true, allf = true;
        #pragma unroll 8
        for (int i = 0; i < 64; i++) {
            unsigned int w = mw[i];
            all01 &= (w == 0u || w == 1u);
            allf  &= (w == 0u || w == 0x3f800000u);
        }
        s_init[0] = (all01 || allf) ? 1 : 0;   // 1 = 4-byte elements, 0 = 1-byte
        s_init[1] = decode_scalar(start_raw[b], N);
    }
    __syncthreads();
    const int word_mode = s_init[0];

    // ---- load mask into shared, count unvisited ----
    int cnt = 0;
    if (word_mode) {
        const unsigned int* m32 = (const unsigned int*)mraw + (size_t)b * N;
        for (int i = tid; i < N && i < MSK_CAP; i += NTHREADS) {
            unsigned char m = (m32[i] != 0u) ? 1 : 0;   // covers int 1 and float 1.0 bits
            s_msk[i] = m;
            cnt += (m == 0);
        }
    } else {
        const unsigned char* m8 = mraw + (size_t)b * N;
        for (int i = tid; i < N && i < MSK_CAP; i += NTHREADS) {
            unsigned char m = m8[i] ? 1 : 0;
            s_msk[i] = m;
            cnt += (m == 0);
        }
    }
    for (int i = N + tid; i < MSK_CAP; i += NTHREADS) s_msk[i] = 1;  // pad region = visited

    #pragma unroll
    for (int o = 16; o > 0; o >>= 1) cnt += __shfl_down_sync(0xffffffffu, cnt, o);
    if (lane == 0) s_warpcnt[wid] = cnt;
    __syncthreads();
    if (tid == 0) {
        int r = 0;
        #pragma unroll
        for (int w = 0; w < NWARPS; w++) r += s_warpcnt[w];
        s_init[2] = r;
        pred_len[b] = (float)r;
    }
    __syncthreads();

    int rem   = s_init[2];
    int point = s_init[1];

    // ---- serial greedy loop: one __syncthreads per iteration ----
    int step = 0;
    while (rem > 0) {
        const float* __restrict__ row = D + (size_t)point * N;
        const int p = step & 1;

        unsigned long long best = ~0ull;

        // each thread handles 4 consecutive elements (one LDG.128 + one LDS.32)
        for (int base = tid * 4; base < N; base += NTHREADS * 4) {
            if (base + 3 < N) {
                float4 v = *reinterpret_cast<const float4*>(row + base);
                unsigned int mw = *reinterpret_cast<const unsigned int*>(s_msk + base);
                float v0 = (mw & 0x000000ffu) ? BIGF : v.x;
                float v1 = (mw & 0x0000ff00u) ? BIGF : v.y;
                float v2 = (mw & 0x00ff0000u) ? BIGF : v.z;
                float v3 = (mw & 0xff000000u) ? BIGF : v.w;
                unsigned long long k0 = ((unsigned long long)__float_as_uint(v0) << 32) | (unsigned)(base + 0);
                unsigned long long k1 = ((unsigned long long)__float_as_uint(v1) << 32) | (unsigned)(base + 1);
                unsigned long long k2 = ((unsigned long long)__float_as_uint(v2) << 32) | (unsigned)(base + 2);
                unsigned long long k3 = ((unsigned long long)__float_as_uint(v3) << 32) | (unsigned)(base + 3);
                unsigned long long ka = k0 < k1 ? k0 : k1;
                unsigned long long kb = k2 < k3 ? k2 : k3;
                unsigned long long kc = ka < kb ? ka : kb;
                best = kc < best ? kc : best;
            } else {
                for (int j = base; j < N; j++) {
                    float v = s_msk[j] ? BIGF : row[j];
                    unsigned long long k = ((unsigned long long)__float_as_uint(v) << 32) | (unsigned)j;
                    best = k < best ? k : best;
                }
            }
        }

        // warp reduce (min of packed keys)
        #pragma unroll
        for (int o = 16; o > 0; o >>= 1) {
            unsigned long long other = __shfl_down_sync(0xffffffffu, best, o);
            best = other < best ? other : best;
        }
        if (lane == 0) s_partial[p][wid] = best;
        __syncthreads();

        // every thread reduces the 8 partials (redundant, but removes 2nd barrier)
        unsigned long long bb = s_partial[p][0];
        #pragma unroll
        for (int w = 1; w < NWARPS; w++) {
            unsigned long long q = s_partial[p][w];
            bb = q < bb ? q : bb;
        }
        int idx = (int)(bb & 0xffffffffu);
        s_msk[idx] = 1;          // every thread writes the same value -> self-visible next iter
        point = idx;
        rem--;
        if (tid == 0) pred_b[step] = (float)idx;   // fire-and-forget STG (float32 output!)
        step++;
        // WAR on s_partial[p] safe: overwrite of this parity buffer is past the next barrier
    }

    // ---- pad fill for inactive steps ----
    const float padf = (float)pad;
    for (int s = step + tid; s < N; s += NTHREADS) pred_b[s] = padf;
}

extern "C" void kernel_launch(void* const* d_in, const int* in_sizes, int n_in,
                              void* d_out, int out_size)
{
    // ---- identify inputs by size (order-independent) ----
    int di = 0;
    for (int i = 1; i < n_in; i++)
        if (in_sizes[i] > in_sizes[di]) di = i;              // distance = largest (B*N*N)

    int mi = -1;
    for (int i = 0; i < n_in; i++) {
        if (i == di) continue;
        if (mi < 0 || in_sizes[i] > in_sizes[mi]) mi = i;    // mask = largest remaining (B*N)
    }

    const long long S_d = in_sizes[di];
    const long long S_m = in_sizes[mi];
    const int N = (int)(S_d / S_m);                          // (B*N*N)/(B*N)
    const int B = (int)(S_m / N);

    int si = -1, pi = -1;
    for (int i = 0; i < n_in; i++) {
        if (i == di || i == mi) continue;
        if (in_sizes[i] == B) si = i;                        // start_idx (B,)
        else if (in_sizes[i] == 1) pi = i;                   // pad_value scalar
    }

    const float*         distance  = (const float*)d_in[di];
    const unsigned char* mask      = (const unsigned char*)d_in[mi];
    const unsigned int*  start_raw = (const unsigned int*)d_in[si];
    const unsigned int*  pad_raw   = (pi >= 0) ? (const unsigned int*)d_in[pi] : nullptr;

    float* pred     = (float*)d_out;          // (B, N) — output dtype is float32
    float* pred_len = pred + (size_t)B * N;   // (B,)

    greedy_nn_kernel<<<B, NTHREADS>>>(distance, mask, start_raw, pad_raw,
                                      pred, pred_len, N);
}